// round 13
// baseline (speedup 1.0000x reference)
#include <cuda_runtime.h>
#include <cuda_bf16.h>
#include <cstdint>
#include <cstddef>

// Problem constants (fixed by the dataset)
#define KCODES   8192
#define DDIM     512
#define NROWS    32768        // B*N = 8*4096
#define BND_ELEMS 16777216ULL // B*N*D

// GEMM tiling
#define TM 128
#define TN 128
#define BK 32
#define NCHUNK (DDIM / BK)    // 16
#define ROWP 40               // smem row pitch in bf16 elems (80B, 16B-aligned)
#define CSLOTS 128
#define MARGIN 2e-3f          // >> score window (~9e-4) + bin ulp(512)=6.1e-5

// Scratch (no cudaMalloc allowed). Only touched from device code.
__device__ unsigned long long g_minpair[NROWS];
__device__ float g_cbsq[KCODES];
__device__ float g_xsq[NROWS];
__device__ float g_amin[NROWS];
__device__ int   g_cnt[NROWS];
__device__ int   g_ovf[NROWS];
__device__ unsigned long long g_cand[(size_t)NROWS * CSLOTS];
__device__ __nv_bfloat16 g_zh[(size_t)NROWS * DDIM];
__device__ __nv_bfloat16 g_cbh[(size_t)KCODES * DDIM];

// ---------------------------------------------------------------------------
// helpers
// ---------------------------------------------------------------------------
__device__ __forceinline__ uint32_t smem_to_u32(const void* p) {
    uint32_t a;
    asm("{ .reg .u64 t; cvta.to.shared.u64 t, %1; cvt.u32.u64 %0, t; }"
        : "=r"(a) : "l"(p));
    return a;
}

__device__ __forceinline__ unsigned int forder(float f) {
    unsigned int u = __float_as_uint(f);
    return (u & 0x80000000u) ? ~u : (u | 0x80000000u);
}

__device__ __forceinline__ void ldmx4(uint32_t& r0, uint32_t& r1,
                                      uint32_t& r2, uint32_t& r3, uint32_t addr) {
    asm volatile("ldmatrix.sync.aligned.m8n8.x4.shared.b16 {%0,%1,%2,%3}, [%4];"
                 : "=r"(r0), "=r"(r1), "=r"(r2), "=r"(r3) : "r"(addr));
}

__device__ __forceinline__ void mma16816(float* d, const uint32_t* a,
                                         const uint32_t* b) {
    asm volatile(
        "mma.sync.aligned.m16n8k16.row.col.f32.bf16.bf16.f32 "
        "{%0,%1,%2,%3}, {%4,%5,%6,%7}, {%8,%9}, {%0,%1,%2,%3};"
        : "+f"(d[0]), "+f"(d[1]), "+f"(d[2]), "+f"(d[3])
        : "r"(a[0]), "r"(a[1]), "r"(a[2]), "r"(a[3]), "r"(b[0]), "r"(b[1]));
}

// exact sequential fp32 dot + reference rounding chain -> packed score|k
__device__ __forceinline__ unsigned long long exact_pack(const float* __restrict__ zr,
                                                         const float* __restrict__ cbr,
                                                         int row, int k) {
    float acc = 0.0f;
    #pragma unroll 8
    for (int d = 0; d < DDIM; d += 4) {
        float4 a = *reinterpret_cast<const float4*>(zr + d);
        float4 b = *reinterpret_cast<const float4*>(cbr + d);
        acc = __fmaf_rn(a.x, b.x, acc);
        acc = __fmaf_rn(a.y, b.y, acc);
        acc = __fmaf_rn(a.z, b.z, acc);
        acc = __fmaf_rn(a.w, b.w, acc);
    }
    float t = __fadd_rn(g_cbsq[k], g_xsq[row]);
    float s = __fadd_rn(t, __fmul_rn(2.0f, acc));
    return ((unsigned long long)forder(s) << 32) | (unsigned int)k;
}

// ---------------------------------------------------------------------------
// kernel 0: reset per-replay state
// ---------------------------------------------------------------------------
__global__ void vq_init_kernel() {
    int i = blockIdx.x * blockDim.x + threadIdx.x;
    if (i < NROWS) {
        g_minpair[i] = 0xFFFFFFFFFFFFFFFFULL;
        g_amin[i] = __int_as_float(0x7F800000);  // +inf
        g_cnt[i] = 0;
        g_ovf[i] = 0;
    }
}

// ---------------------------------------------------------------------------
// kernel 1: squared norms, STRICTLY SEQUENTIAL fp32: s = fl(s + fl(v*v)).
// ---------------------------------------------------------------------------
__device__ __forceinline__ float sqsum_row_body(const float* __restrict__ src,
                                                float tile[128][33], int tid,
                                                int r0) {
    float s = 0.0f;
    for (int c0 = 0; c0 < DDIM; c0 += 32) {
        #pragma unroll
        for (int i = tid; i < 128 * 32; i += 128) {
            int rr = i >> 5;
            int cc = i & 31;
            tile[rr][cc] = src[(size_t)(r0 + rr) * DDIM + c0 + cc];
        }
        __syncthreads();
        #pragma unroll
        for (int cc = 0; cc < 32; cc++) {
            float v = tile[tid][cc];
            s = __fadd_rn(s, __fmul_rn(v, v));
        }
        __syncthreads();
    }
    return s;
}

__global__ void __launch_bounds__(128)
vq_xsq_kernel(const float* __restrict__ src) {
    __shared__ float tile[128][33];
    int r0 = blockIdx.x * 128;
    float s = sqsum_row_body(src, tile, threadIdx.x, r0);
    g_xsq[r0 + threadIdx.x] = s;
}

__global__ void __launch_bounds__(128)
vq_cbsq_kernel(const float* __restrict__ src) {
    __shared__ float tile[128][33];
    int r0 = blockIdx.x * 128;
    float s = sqsum_row_body(src, tile, threadIdx.x, r0);
    g_cbsq[r0 + threadIdx.x] = s;
}

// ---------------------------------------------------------------------------
// kernel 2: fp32 -> bf16 conversions
// ---------------------------------------------------------------------------
__global__ void __launch_bounds__(256)
vq_cvt_z_kernel(const float* __restrict__ z) {
    size_t i = ((size_t)blockIdx.x * 256 + threadIdx.x) * 4;
    float4 v = *reinterpret_cast<const float4*>(z + i);
    __nv_bfloat16 o[4] = { __float2bfloat16(v.x), __float2bfloat16(v.y),
                           __float2bfloat16(v.z), __float2bfloat16(v.w) };
    *reinterpret_cast<uint2*>(&g_zh[i]) = *reinterpret_cast<uint2*>(o);
}

__global__ void __launch_bounds__(256)
vq_cvt_cb_kernel(const float* __restrict__ cb) {
    size_t i = ((size_t)blockIdx.x * 256 + threadIdx.x) * 4;
    float4 v = *reinterpret_cast<const float4*>(cb + i);
    __nv_bfloat16 o[4] = { __float2bfloat16(v.x), __float2bfloat16(v.y),
                           __float2bfloat16(v.z), __float2bfloat16(v.w) };
    *reinterpret_cast<uint2*>(&g_cbh[i]) = *reinterpret_cast<uint2*>(o);
}

// ---------------------------------------------------------------------------
// kernel 3: bf16 HMMA GEMM (mma.sync m16n8k16, fp32 acc) + candidate epilogue
//   8 warps = 2(M) x 4(N); warp tile 64x32; BK=32 double-buffered.
//   __launch_bounds__(256, 1): 64 fp32 accumulators + fragments + prefetch
//   need ~200 regs — the (256,2) cap of 128 regs caused catastrophic local-
//   memory spilling of the accumulators in R12 (127 ms).
// ---------------------------------------------------------------------------
__global__ void __launch_bounds__(256, 1)
vq_mma_kernel() {
    __shared__ __align__(16) __nv_bfloat16 As[2][TM][ROWP];
    __shared__ __align__(16) __nv_bfloat16 Bs[2][TN][ROWP];
    __shared__ float s_rowmin[TM][4];
    __shared__ float s_thr[TM];

    const int tid = threadIdx.x;
    const int lane = tid & 31;
    const int wid = tid >> 5;
    const int warp_m = wid >> 2;   // 0..1
    const int warp_n = wid & 3;    // 0..3
    const int m0 = blockIdx.y * TM;
    const int k0 = blockIdx.x * TN;

    const uint32_t Abase = smem_to_u32(&As[0][0][0]);
    const uint32_t Bbase = smem_to_u32(&Bs[0][0][0]);
    const uint32_t bufstride = (uint32_t)(TM * ROWP * 2);  // bytes per buffer

    float acc[4][4][4];
    #pragma unroll
    for (int mi = 0; mi < 4; mi++)
        #pragma unroll
        for (int ni = 0; ni < 4; ni++)
            #pragma unroll
            for (int j = 0; j < 4; j++) acc[mi][ni][j] = 0.0f;

    // loader: per chunk each thread moves 2x16B of A and 2x16B of B
    {
        #pragma unroll
        for (int t = 0; t < 2; t++) {
            int u = tid + t * 256;
            int row = u >> 2, seg = u & 3;
            uint4 va = *reinterpret_cast<const uint4*>(
                &g_zh[(size_t)(m0 + row) * DDIM + seg * 8]);
            uint4 vb = *reinterpret_cast<const uint4*>(
                &g_cbh[(size_t)(k0 + row) * DDIM + seg * 8]);
            *reinterpret_cast<uint4*>(&As[0][row][seg * 8]) = va;
            *reinterpret_cast<uint4*>(&Bs[0][row][seg * 8]) = vb;
        }
    }
    __syncthreads();

    int buf = 0;
    #pragma unroll 1
    for (int ch = 1; ch <= NCHUNK; ch++) {
        const bool more = (ch < NCHUNK);
        uint4 pa[2], pb[2];
        if (more) {
            #pragma unroll
            for (int t = 0; t < 2; t++) {
                int u = tid + t * 256;
                int row = u >> 2, seg = u & 3;
                pa[t] = *reinterpret_cast<const uint4*>(
                    &g_zh[(size_t)(m0 + row) * DDIM + ch * BK + seg * 8]);
                pb[t] = *reinterpret_cast<const uint4*>(
                    &g_cbh[(size_t)(k0 + row) * DDIM + ch * BK + seg * 8]);
            }
        }

        // compute on current buffer: 2 k16 steps
        #pragma unroll
        for (int kst = 0; kst < 2; kst++) {
            uint32_t afr[4][4];
            #pragma unroll
            for (int mi = 0; mi < 4; mi++) {
                uint32_t addr = Abase + buf * bufstride +
                    (uint32_t)(((warp_m * 64 + mi * 16 + (lane & 15)) * ROWP +
                                kst * 16 + (lane >> 4) * 8) * 2);
                ldmx4(afr[mi][0], afr[mi][1], afr[mi][2], afr[mi][3], addr);
            }
            uint32_t bfr[2][4];
            #pragma unroll
            for (int nj = 0; nj < 2; nj++) {
                int nrow = warp_n * 32 + nj * 16 + (lane & 7) + ((lane >> 4) & 1) * 8;
                int kcol = kst * 16 + ((lane >> 3) & 1) * 8;
                uint32_t addr = Bbase + buf * bufstride +
                    (uint32_t)((nrow * ROWP + kcol) * 2);
                ldmx4(bfr[nj][0], bfr[nj][1], bfr[nj][2], bfr[nj][3], addr);
            }
            #pragma unroll
            for (int mi = 0; mi < 4; mi++)
                #pragma unroll
                for (int ni = 0; ni < 4; ni++)
                    mma16816(acc[mi][ni], afr[mi], &bfr[ni >> 1][(ni & 1) * 2]);
        }

        if (more) {
            int nxt = buf ^ 1;
            #pragma unroll
            for (int t = 0; t < 2; t++) {
                int u = tid + t * 256;
                int row = u >> 2, seg = u & 3;
                *reinterpret_cast<uint4*>(&As[nxt][row][seg * 8]) = pa[t];
                *reinterpret_cast<uint4*>(&Bs[nxt][row][seg * 8]) = pb[t];
            }
            __syncthreads();
            buf = nxt;
        }
    }

    // ---- epilogue ----
    float xs[8];
    #pragma unroll
    for (int mi = 0; mi < 4; mi++) {
        xs[mi * 2 + 0] = g_xsq[m0 + warp_m * 64 + mi * 16 + (lane >> 2)];
        xs[mi * 2 + 1] = g_xsq[m0 + warp_m * 64 + mi * 16 + (lane >> 2) + 8];
    }
    float cbq[8];
    #pragma unroll
    for (int ni = 0; ni < 4; ni++) {
        cbq[ni * 2 + 0] = g_cbsq[k0 + warp_n * 32 + ni * 8 + (lane & 3) * 2];
        cbq[ni * 2 + 1] = g_cbsq[k0 + warp_n * 32 + ni * 8 + (lane & 3) * 2 + 1];
    }
    #pragma unroll
    for (int mi = 0; mi < 4; mi++) {
        float rmin0 = __int_as_float(0x7F800000);
        float rmin1 = __int_as_float(0x7F800000);
        #pragma unroll
        for (int ni = 0; ni < 4; ni++) {
            acc[mi][ni][0] = (cbq[ni * 2 + 0] + xs[mi * 2]) + 2.0f * acc[mi][ni][0];
            acc[mi][ni][1] = (cbq[ni * 2 + 1] + xs[mi * 2]) + 2.0f * acc[mi][ni][1];
            acc[mi][ni][2] = (cbq[ni * 2 + 0] + xs[mi * 2 + 1]) + 2.0f * acc[mi][ni][2];
            acc[mi][ni][3] = (cbq[ni * 2 + 1] + xs[mi * 2 + 1]) + 2.0f * acc[mi][ni][3];
            rmin0 = fminf(rmin0, fminf(acc[mi][ni][0], acc[mi][ni][1]));
            rmin1 = fminf(rmin1, fminf(acc[mi][ni][2], acc[mi][ni][3]));
        }
        #pragma unroll
        for (int m = 1; m <= 2; m <<= 1) {
            rmin0 = fminf(rmin0, __shfl_xor_sync(0xFFFFFFFFu, rmin0, m));
            rmin1 = fminf(rmin1, __shfl_xor_sync(0xFFFFFFFFu, rmin1, m));
        }
        if ((lane & 3) == 0) {
            s_rowmin[warp_m * 64 + mi * 16 + (lane >> 2)][warp_n] = rmin0;
            s_rowmin[warp_m * 64 + mi * 16 + (lane >> 2) + 8][warp_n] = rmin1;
        }
    }
    __syncthreads();
    if (tid < TM) {
        float g = fminf(fminf(s_rowmin[tid][0], s_rowmin[tid][1]),
                        fminf(s_rowmin[tid][2], s_rowmin[tid][3]));
        atomicMin((int*)&g_amin[m0 + tid], __float_as_int(g));  // scores > 0
        s_thr[tid] = g + MARGIN;
    }
    __syncthreads();

    // candidate push
    #pragma unroll
    for (int mi = 0; mi < 4; mi++) {
        #pragma unroll
        for (int h = 0; h < 2; h++) {
            int row = warp_m * 64 + mi * 16 + (lane >> 2) + h * 8;
            float thr = s_thr[row];
            int grow = m0 + row;
            #pragma unroll
            for (int ni = 0; ni < 4; ni++) {
                #pragma unroll
                for (int c = 0; c < 2; c++) {
                    float s = acc[mi][ni][h * 2 + c];
                    if (s <= thr) {
                        int k = k0 + warp_n * 32 + ni * 8 + (lane & 3) * 2 + c;
                        int slot = atomicAdd(&g_cnt[grow], 1);
                        if (slot < CSLOTS) {
                            g_cand[(size_t)grow * CSLOTS + slot] =
                                ((unsigned long long)__float_as_uint(s) << 32) |
                                (unsigned int)k;
                        } else {
                            g_ovf[grow] = 1;
                        }
                    }
                }
            }
        }
    }
}

// ---------------------------------------------------------------------------
// kernel 4: filter candidates vs global approx min; exact fp32 rescan
// ---------------------------------------------------------------------------
__global__ void __launch_bounds__(256)
vq_filter_kernel(const float* __restrict__ z, const float* __restrict__ cb) {
    const int row = blockIdx.x * 8 + (threadIdx.x >> 5);
    const int lane = threadIdx.x & 31;
    const float thr = g_amin[row] + MARGIN;
    int cnt = g_cnt[row];
    if (cnt > CSLOTS) cnt = CSLOTS;
    const float* zr = z + (size_t)row * DDIM;
    for (int i = lane; i < cnt; i += 32) {
        unsigned long long e = g_cand[(size_t)row * CSLOTS + i];
        float s = __uint_as_float((unsigned int)(e >> 32));
        if (s <= thr) {
            int k = (int)(e & 0xFFFFFFFFu);
            unsigned long long p = exact_pack(zr, cb + (size_t)k * DDIM, row, k);
            atomicMin(&g_minpair[row], p);
        }
    }
}

// ---------------------------------------------------------------------------
// kernel 5: overflow fallback — full exact scan (expected: no rows)
// ---------------------------------------------------------------------------
__global__ void __launch_bounds__(256)
vq_ovf_kernel(const float* __restrict__ z, const float* __restrict__ cb) {
    const int row = blockIdx.x * 8 + (threadIdx.x >> 5);
    const int lane = threadIdx.x & 31;
    if (!g_ovf[row]) return;
    const float* zr = z + (size_t)row * DDIM;
    for (int k = lane; k < KCODES; k += 32) {
        unsigned long long p = exact_pack(zr, cb + (size_t)k * DDIM, row, k);
        atomicMin(&g_minpair[row], p);
    }
}

// ---------------------------------------------------------------------------
// kernel 6: gather codes (twice) + write idx as float
// ---------------------------------------------------------------------------
__global__ void vq_gather_kernel(const float* __restrict__ cb,
                                 float* __restrict__ out) {
    int row = blockIdx.x;
    unsigned long long pair = g_minpair[row];
    unsigned int k = (unsigned int)(pair & 0xFFFFFFFFu);

    const float4* src = reinterpret_cast<const float4*>(cb + (size_t)k * DDIM);
    float4* o1 = reinterpret_cast<float4*>(out + (size_t)row * DDIM);
    float4* o2 = reinterpret_cast<float4*>(out + BND_ELEMS + (size_t)row * DDIM);
    float4 v = src[threadIdx.x];
    o1[threadIdx.x] = v;
    o2[threadIdx.x] = v;
    if (threadIdx.x == 0) {
        out[2 * BND_ELEMS + (size_t)row] = (float)k;
    }
}

// ---------------------------------------------------------------------------
// launch
// ---------------------------------------------------------------------------
extern "C" void kernel_launch(void* const* d_in, const int* in_sizes, int n_in,
                              void* d_out, int out_size) {
    (void)out_size;
    const float* z  = (const float*)d_in[0];
    const float* cb = (const float*)d_in[1];
    if (n_in >= 2 && in_sizes[0] < in_sizes[1]) {
        const float* t = z; z = cb; cb = t;
    }
    float* out = (float*)d_out;

    vq_init_kernel<<<NROWS / 256, 256>>>();
    vq_cbsq_kernel<<<KCODES / 128, 128>>>(cb);
    vq_xsq_kernel<<<NROWS / 128, 128>>>(z);
    vq_cvt_z_kernel<<<(NROWS * DDIM) / (256 * 4), 256>>>(z);
    vq_cvt_cb_kernel<<<(KCODES * DDIM) / (256 * 4), 256>>>(cb);

    dim3 grid(KCODES / TN, NROWS / TM);   // (64, 256)
    vq_mma_kernel<<<grid, 256>>>();

    vq_filter_kernel<<<NROWS / 8, 256>>>(z, cb);
    vq_ovf_kernel<<<NROWS / 8, 256>>>(z, cb);
    vq_gather_kernel<<<NROWS, 128>>>(cb, out);
}

// round 14
// speedup vs baseline: 49.6266x; 49.6266x over previous
#include <cuda_runtime.h>
#include <cuda_bf16.h>
#include <cstdint>
#include <cstddef>

// Problem constants (fixed by the dataset)
#define KCODES   8192
#define DDIM     512
#define NROWS    32768        // B*N = 8*4096
#define BND_ELEMS 16777216ULL // B*N*D

// GEMM tiling
#define TM 128
#define TN 128
#define BK 32
#define NCHUNK (DDIM / BK)    // 16
#define ROWP 40               // smem row pitch in bf16 elems (80B, 16B-aligned)
#define CSLOTS 256
// Guaranteed-sufficient push/filter margin: bin(6.1e-5) + 2*worst-case bf16
// score error (~4.6e-4) = 5.2e-4; use 1e-3 for 2x headroom.
#define MARGIN 1e-3f

// Scratch (no cudaMalloc allowed). Only touched from device code.
__device__ unsigned long long g_minpair[NROWS];
__device__ float g_cbsq[KCODES];
__device__ float g_xsq[NROWS];
__device__ float g_amin[NROWS];
__device__ int   g_cnt[NROWS];
__device__ int   g_ovf[NROWS];
__device__ unsigned long long g_cand[(size_t)NROWS * CSLOTS];
__device__ __nv_bfloat16 g_zh[(size_t)NROWS * DDIM];
__device__ __nv_bfloat16 g_cbh[(size_t)KCODES * DDIM];

// ---------------------------------------------------------------------------
// helpers
// ---------------------------------------------------------------------------
__device__ __forceinline__ uint32_t smem_to_u32(const void* p) {
    uint32_t a;
    asm("{ .reg .u64 t; cvta.to.shared.u64 t, %1; cvt.u32.u64 %0, t; }"
        : "=r"(a) : "l"(p));
    return a;
}

__device__ __forceinline__ unsigned int forder(float f) {
    unsigned int u = __float_as_uint(f);
    return (u & 0x80000000u) ? ~u : (u | 0x80000000u);
}

__device__ __forceinline__ void ldmx4(uint32_t& r0, uint32_t& r1,
                                      uint32_t& r2, uint32_t& r3, uint32_t addr) {
    asm volatile("ldmatrix.sync.aligned.m8n8.x4.shared.b16 {%0,%1,%2,%3}, [%4];"
                 : "=r"(r0), "=r"(r1), "=r"(r2), "=r"(r3) : "r"(addr));
}

__device__ __forceinline__ void mma16816(float* d, const uint32_t* a,
                                         const uint32_t* b) {
    asm volatile(
        "mma.sync.aligned.m16n8k16.row.col.f32.bf16.bf16.f32 "
        "{%0,%1,%2,%3}, {%4,%5,%6,%7}, {%8,%9}, {%0,%1,%2,%3};"
        : "+f"(d[0]), "+f"(d[1]), "+f"(d[2]), "+f"(d[3])
        : "r"(a[0]), "r"(a[1]), "r"(a[2]), "r"(a[3]), "r"(b[0]), "r"(b[1]));
}

// exact sequential fp32 dot + reference rounding chain -> packed score|k
__device__ __forceinline__ unsigned long long exact_pack(const float* __restrict__ zr,
                                                         const float* __restrict__ cbr,
                                                         int row, int k) {
    float acc = 0.0f;
    #pragma unroll 8
    for (int d = 0; d < DDIM; d += 4) {
        float4 a = *reinterpret_cast<const float4*>(zr + d);
        float4 b = *reinterpret_cast<const float4*>(cbr + d);
        acc = __fmaf_rn(a.x, b.x, acc);
        acc = __fmaf_rn(a.y, b.y, acc);
        acc = __fmaf_rn(a.z, b.z, acc);
        acc = __fmaf_rn(a.w, b.w, acc);
    }
    float t = __fadd_rn(g_cbsq[k], g_xsq[row]);
    float s = __fadd_rn(t, __fmul_rn(2.0f, acc));
    return ((unsigned long long)forder(s) << 32) | (unsigned int)k;
}

// ---------------------------------------------------------------------------
// kernel 0: reset per-replay state
// ---------------------------------------------------------------------------
__global__ void vq_init_kernel() {
    int i = blockIdx.x * blockDim.x + threadIdx.x;
    if (i < NROWS) {
        g_minpair[i] = 0xFFFFFFFFFFFFFFFFULL;
        g_amin[i] = __int_as_float(0x7F800000);  // +inf
        g_cnt[i] = 0;
        g_ovf[i] = 0;
    }
}

// ---------------------------------------------------------------------------
// kernel 1: squared norms, STRICTLY SEQUENTIAL fp32: s = fl(s + fl(v*v)).
// ---------------------------------------------------------------------------
__device__ __forceinline__ float sqsum_row_body(const float* __restrict__ src,
                                                float tile[128][33], int tid,
                                                int r0) {
    float s = 0.0f;
    for (int c0 = 0; c0 < DDIM; c0 += 32) {
        #pragma unroll
        for (int i = tid; i < 128 * 32; i += 128) {
            int rr = i >> 5;
            int cc = i & 31;
            tile[rr][cc] = src[(size_t)(r0 + rr) * DDIM + c0 + cc];
        }
        __syncthreads();
        #pragma unroll
        for (int cc = 0; cc < 32; cc++) {
            float v = tile[tid][cc];
            s = __fadd_rn(s, __fmul_rn(v, v));
        }
        __syncthreads();
    }
    return s;
}

__global__ void __launch_bounds__(128)
vq_xsq_kernel(const float* __restrict__ src) {
    __shared__ float tile[128][33];
    int r0 = blockIdx.x * 128;
    float s = sqsum_row_body(src, tile, threadIdx.x, r0);
    g_xsq[r0 + threadIdx.x] = s;
}

__global__ void __launch_bounds__(128)
vq_cbsq_kernel(const float* __restrict__ src) {
    __shared__ float tile[128][33];
    int r0 = blockIdx.x * 128;
    float s = sqsum_row_body(src, tile, threadIdx.x, r0);
    g_cbsq[r0 + threadIdx.x] = s;
}

// ---------------------------------------------------------------------------
// kernel 2: fp32 -> bf16 conversions
// ---------------------------------------------------------------------------
__global__ void __launch_bounds__(256)
vq_cvt_z_kernel(const float* __restrict__ z) {
    size_t i = ((size_t)blockIdx.x * 256 + threadIdx.x) * 4;
    float4 v = *reinterpret_cast<const float4*>(z + i);
    __nv_bfloat16 o[4] = { __float2bfloat16(v.x), __float2bfloat16(v.y),
                           __float2bfloat16(v.z), __float2bfloat16(v.w) };
    *reinterpret_cast<uint2*>(&g_zh[i]) = *reinterpret_cast<uint2*>(o);
}

__global__ void __launch_bounds__(256)
vq_cvt_cb_kernel(const float* __restrict__ cb) {
    size_t i = ((size_t)blockIdx.x * 256 + threadIdx.x) * 4;
    float4 v = *reinterpret_cast<const float4*>(cb + i);
    __nv_bfloat16 o[4] = { __float2bfloat16(v.x), __float2bfloat16(v.y),
                           __float2bfloat16(v.z), __float2bfloat16(v.w) };
    *reinterpret_cast<uint2*>(&g_cbh[i]) = *reinterpret_cast<uint2*>(o);
}

// ---------------------------------------------------------------------------
// kernel 3: bf16 HMMA GEMM (mma.sync m16n8k16, fp32 acc) + candidate epilogue
//   8 warps = 2(M) x 4(N); warp tile 64x32; BK=32 double-buffered.
//   The true quantized winner k* always satisfies
//   approx_s(k*) <= local_min(tile(k*)) + bin + 2e  (= 5.2e-4 < MARGIN),
//   so pushing within MARGIN of the TILE-local min is a guaranteed superset.
// ---------------------------------------------------------------------------
__global__ void __launch_bounds__(256, 1)
vq_mma_kernel() {
    __shared__ __align__(16) __nv_bfloat16 As[2][TM][ROWP];
    __shared__ __align__(16) __nv_bfloat16 Bs[2][TN][ROWP];
    __shared__ float s_rowmin[TM][4];
    __shared__ float s_thr[TM];

    const int tid = threadIdx.x;
    const int lane = tid & 31;
    const int wid = tid >> 5;
    const int warp_m = wid >> 2;   // 0..1
    const int warp_n = wid & 3;    // 0..3
    const int m0 = blockIdx.y * TM;
    const int k0 = blockIdx.x * TN;

    const uint32_t Abase = smem_to_u32(&As[0][0][0]);
    const uint32_t Bbase = smem_to_u32(&Bs[0][0][0]);
    const uint32_t bufstride = (uint32_t)(TM * ROWP * 2);  // bytes per buffer

    float acc[4][4][4];
    #pragma unroll
    for (int mi = 0; mi < 4; mi++)
        #pragma unroll
        for (int ni = 0; ni < 4; ni++)
            #pragma unroll
            for (int j = 0; j < 4; j++) acc[mi][ni][j] = 0.0f;

    // prologue: fill buffer 0
    {
        #pragma unroll
        for (int t = 0; t < 2; t++) {
            int u = tid + t * 256;
            int row = u >> 2, seg = u & 3;
            uint4 va = *reinterpret_cast<const uint4*>(
                &g_zh[(size_t)(m0 + row) * DDIM + seg * 8]);
            uint4 vb = *reinterpret_cast<const uint4*>(
                &g_cbh[(size_t)(k0 + row) * DDIM + seg * 8]);
            *reinterpret_cast<uint4*>(&As[0][row][seg * 8]) = va;
            *reinterpret_cast<uint4*>(&Bs[0][row][seg * 8]) = vb;
        }
    }
    __syncthreads();

    int buf = 0;
    #pragma unroll 1
    for (int ch = 1; ch <= NCHUNK; ch++) {
        const bool more = (ch < NCHUNK);
        uint4 pa[2], pb[2];
        if (more) {
            #pragma unroll
            for (int t = 0; t < 2; t++) {
                int u = tid + t * 256;
                int row = u >> 2, seg = u & 3;
                pa[t] = *reinterpret_cast<const uint4*>(
                    &g_zh[(size_t)(m0 + row) * DDIM + ch * BK + seg * 8]);
                pb[t] = *reinterpret_cast<const uint4*>(
                    &g_cbh[(size_t)(k0 + row) * DDIM + ch * BK + seg * 8]);
            }
        }

        // compute on current buffer: 2 k16 steps
        #pragma unroll
        for (int kst = 0; kst < 2; kst++) {
            uint32_t afr[4][4];
            #pragma unroll
            for (int mi = 0; mi < 4; mi++) {
                uint32_t addr = Abase + buf * bufstride +
                    (uint32_t)(((warp_m * 64 + mi * 16 + (lane & 15)) * ROWP +
                                kst * 16 + (lane >> 4) * 8) * 2);
                ldmx4(afr[mi][0], afr[mi][1], afr[mi][2], afr[mi][3], addr);
            }
            uint32_t bfr[2][4];
            #pragma unroll
            for (int nj = 0; nj < 2; nj++) {
                int nrow = warp_n * 32 + nj * 16 + (lane & 7) + ((lane >> 4) & 1) * 8;
                int kcol = kst * 16 + ((lane >> 3) & 1) * 8;
                uint32_t addr = Bbase + buf * bufstride +
                    (uint32_t)((nrow * ROWP + kcol) * 2);
                ldmx4(bfr[nj][0], bfr[nj][1], bfr[nj][2], bfr[nj][3], addr);
            }
            #pragma unroll
            for (int mi = 0; mi < 4; mi++)
                #pragma unroll
                for (int ni = 0; ni < 4; ni++)
                    mma16816(acc[mi][ni], afr[mi], &bfr[ni >> 1][(ni & 1) * 2]);
        }

        if (more) {
            int nxt = buf ^ 1;
            #pragma unroll
            for (int t = 0; t < 2; t++) {
                int u = tid + t * 256;
                int row = u >> 2, seg = u & 3;
                *reinterpret_cast<uint4*>(&As[nxt][row][seg * 8]) = pa[t];
                *reinterpret_cast<uint4*>(&Bs[nxt][row][seg * 8]) = pb[t];
            }
            __syncthreads();
            buf = nxt;
        }
    }

    // ---- epilogue ----
    float xs[8];
    #pragma unroll
    for (int mi = 0; mi < 4; mi++) {
        xs[mi * 2 + 0] = g_xsq[m0 + warp_m * 64 + mi * 16 + (lane >> 2)];
        xs[mi * 2 + 1] = g_xsq[m0 + warp_m * 64 + mi * 16 + (lane >> 2) + 8];
    }
    float cbq[8];
    #pragma unroll
    for (int ni = 0; ni < 4; ni++) {
        cbq[ni * 2 + 0] = g_cbsq[k0 + warp_n * 32 + ni * 8 + (lane & 3) * 2];
        cbq[ni * 2 + 1] = g_cbsq[k0 + warp_n * 32 + ni * 8 + (lane & 3) * 2 + 1];
    }
    #pragma unroll
    for (int mi = 0; mi < 4; mi++) {
        float rmin0 = __int_as_float(0x7F800000);
        float rmin1 = __int_as_float(0x7F800000);
        #pragma unroll
        for (int ni = 0; ni < 4; ni++) {
            acc[mi][ni][0] = (cbq[ni * 2 + 0] + xs[mi * 2]) + 2.0f * acc[mi][ni][0];
            acc[mi][ni][1] = (cbq[ni * 2 + 1] + xs[mi * 2]) + 2.0f * acc[mi][ni][1];
            acc[mi][ni][2] = (cbq[ni * 2 + 0] + xs[mi * 2 + 1]) + 2.0f * acc[mi][ni][2];
            acc[mi][ni][3] = (cbq[ni * 2 + 1] + xs[mi * 2 + 1]) + 2.0f * acc[mi][ni][3];
            rmin0 = fminf(rmin0, fminf(acc[mi][ni][0], acc[mi][ni][1]));
            rmin1 = fminf(rmin1, fminf(acc[mi][ni][2], acc[mi][ni][3]));
        }
        #pragma unroll
        for (int m = 1; m <= 2; m <<= 1) {
            rmin0 = fminf(rmin0, __shfl_xor_sync(0xFFFFFFFFu, rmin0, m));
            rmin1 = fminf(rmin1, __shfl_xor_sync(0xFFFFFFFFu, rmin1, m));
        }
        if ((lane & 3) == 0) {
            s_rowmin[warp_m * 64 + mi * 16 + (lane >> 2)][warp_n] = rmin0;
            s_rowmin[warp_m * 64 + mi * 16 + (lane >> 2) + 8][warp_n] = rmin1;
        }
    }
    __syncthreads();
    if (tid < TM) {
        float g = fminf(fminf(s_rowmin[tid][0], s_rowmin[tid][1]),
                        fminf(s_rowmin[tid][2], s_rowmin[tid][3]));
        atomicMin((int*)&g_amin[m0 + tid], __float_as_int(g));  // scores > 0
        s_thr[tid] = g + MARGIN;
    }
    __syncthreads();

    // candidate push (expected ~2 per tile-row)
    #pragma unroll
    for (int mi = 0; mi < 4; mi++) {
        #pragma unroll
        for (int h = 0; h < 2; h++) {
            int row = warp_m * 64 + mi * 16 + (lane >> 2) + h * 8;
            float thr = s_thr[row];
            int grow = m0 + row;
            #pragma unroll
            for (int ni = 0; ni < 4; ni++) {
                #pragma unroll
                for (int c = 0; c < 2; c++) {
                    float s = acc[mi][ni][h * 2 + c];
                    if (s <= thr) {
                        int k = k0 + warp_n * 32 + ni * 8 + (lane & 3) * 2 + c;
                        int slot = atomicAdd(&g_cnt[grow], 1);
                        if (slot < CSLOTS) {
                            g_cand[(size_t)grow * CSLOTS + slot] =
                                ((unsigned long long)__float_as_uint(s) << 32) |
                                (unsigned int)k;
                        } else {
                            g_ovf[grow] = 1;
                        }
                    }
                }
            }
        }
    }
}

// ---------------------------------------------------------------------------
// kernel 4: filter candidates vs global approx min; exact fp32 rescan
// ---------------------------------------------------------------------------
__global__ void __launch_bounds__(256)
vq_filter_kernel(const float* __restrict__ z, const float* __restrict__ cb) {
    const int row = blockIdx.x * 8 + (threadIdx.x >> 5);
    const int lane = threadIdx.x & 31;
    const float thr = g_amin[row] + MARGIN;
    int cnt = g_cnt[row];
    if (cnt > CSLOTS) cnt = CSLOTS;
    const float* zr = z + (size_t)row * DDIM;
    for (int i = lane; i < cnt; i += 32) {
        unsigned long long e = g_cand[(size_t)row * CSLOTS + i];
        float s = __uint_as_float((unsigned int)(e >> 32));
        if (s <= thr) {
            int k = (int)(e & 0xFFFFFFFFu);
            unsigned long long p = exact_pack(zr, cb + (size_t)k * DDIM, row, k);
            atomicMin(&g_minpair[row], p);
        }
    }
}

// ---------------------------------------------------------------------------
// kernel 5: overflow fallback — full exact scan (expected: zero rows now;
// CSLOTS=256 vs expected ~135 candidates/row)
// ---------------------------------------------------------------------------
__global__ void __launch_bounds__(256)
vq_ovf_kernel(const float* __restrict__ z, const float* __restrict__ cb) {
    const int row = blockIdx.x * 8 + (threadIdx.x >> 5);
    const int lane = threadIdx.x & 31;
    if (!g_ovf[row]) return;
    const float* zr = z + (size_t)row * DDIM;
    for (int k = lane; k < KCODES; k += 32) {
        unsigned long long p = exact_pack(zr, cb + (size_t)k * DDIM, row, k);
        atomicMin(&g_minpair[row], p);
    }
}

// ---------------------------------------------------------------------------
// kernel 6: gather codes (twice) + write idx as float
// ---------------------------------------------------------------------------
__global__ void vq_gather_kernel(const float* __restrict__ cb,
                                 float* __restrict__ out) {
    int row = blockIdx.x;
    unsigned long long pair = g_minpair[row];
    unsigned int k = (unsigned int)(pair & 0xFFFFFFFFu);

    const float4* src = reinterpret_cast<const float4*>(cb + (size_t)k * DDIM);
    float4* o1 = reinterpret_cast<float4*>(out + (size_t)row * DDIM);
    float4* o2 = reinterpret_cast<float4*>(out + BND_ELEMS + (size_t)row * DDIM);
    float4 v = src[threadIdx.x];
    o1[threadIdx.x] = v;
    o2[threadIdx.x] = v;
    if (threadIdx.x == 0) {
        out[2 * BND_ELEMS + (size_t)row] = (float)k;
    }
}

// ---------------------------------------------------------------------------
// launch
// ---------------------------------------------------------------------------
extern "C" void kernel_launch(void* const* d_in, const int* in_sizes, int n_in,
                              void* d_out, int out_size) {
    (void)out_size;
    const float* z  = (const float*)d_in[0];
    const float* cb = (const float*)d_in[1];
    if (n_in >= 2 && in_sizes[0] < in_sizes[1]) {
        const float* t = z; z = cb; cb = t;
    }
    float* out = (float*)d_out;

    vq_init_kernel<<<NROWS / 256, 256>>>();
    vq_cbsq_kernel<<<KCODES / 128, 128>>>(cb);
    vq_xsq_kernel<<<NROWS / 128, 128>>>(z);
    vq_cvt_z_kernel<<<(NROWS * DDIM) / (256 * 4), 256>>>(z);
    vq_cvt_cb_kernel<<<(KCODES * DDIM) / (256 * 4), 256>>>(cb);

    dim3 grid(KCODES / TN, NROWS / TM);   // (64, 256)
    vq_mma_kernel<<<grid, 256>>>();

    vq_filter_kernel<<<NROWS / 8, 256>>>(z, cb);
    vq_ovf_kernel<<<NROWS / 8, 256>>>(z, cb);
    vq_gather_kernel<<<NROWS, 128>>>(cb, out);
}